// round 1
// baseline (speedup 1.0000x reference)
#include <cuda_runtime.h>

#define BATCH 64
#define NJ 21
#define BJ (BATCH * NJ)        // 1344
#define IMG 256

// Seeds: (sx, sy) per (batch, joint)
__device__ int2 g_seeds[BJ];

// w[d] = exp(-d^2 / (2 * 2.5^2)) = exp(-d^2 / 12.5), d = 0..5
__constant__ float c_w[6] = {
    1.0f,
    0.92311634638663580f,   // exp(-0.08)
    0.72614903707369090f,   // exp(-0.32)
    0.48675225595997170f,   // exp(-0.72)
    0.27803730045319410f,   // exp(-1.28)
    0.13533528323661270f    // exp(-2.00)
};

__global__ void seed_kernel(const float* __restrict__ joint) {
    int i = blockIdx.x * blockDim.x + threadIdx.x;
    if (i >= BJ) return;
    // Double precision projection: immune to fast-math substitution and
    // avoids sinf/cosf entirely (cos(atan2(y,x)) = x/rho, sin = y/rho).
    double x = (double)joint[i * 3 + 0];
    double y = (double)joint[i * 3 + 1];
    double z = (double)joint[i * 3 + 2];
    double rho = sqrt(x * x + y * y);
    double theta = atan2(rho, z);
    double r = 128.0 * theta / 1.5707963267948966;  // RADIUS * theta / (pi/2)
    double cphi, sphi;
    if (rho > 0.0) { cphi = x / rho; sphi = y / rho; }
    else           { cphi = 1.0;     sphi = 0.0;     }
    // rint = round-half-to-even, matching jnp.round
    double fx = rint(128.0 + r * cphi);
    double fy = rint(128.0 + r * sphi);
    int sx = (int)fx;
    int sy = (int)fy;
    sx = min(max(sx, 0), IMG - 1);
    sy = min(max(sy, 0), IMG - 1);
    g_seeds[i] = make_int2(sx, sy);
}

// One float4 (4 horizontal pixels) per thread. Flat layout:
//   tid -> x4 = (tid & 63)*4, y = (tid>>6)&255, bj = tid>>14
__global__ void __launch_bounds__(256) hm_kernel(float4* __restrict__ out) {
    unsigned tid = blockIdx.x * blockDim.x + threadIdx.x;
    unsigned x0  = (tid & 63u) << 2;
    unsigned y   = (tid >> 6) & 255u;
    unsigned bj  = tid >> 14;

    int2 s = g_seeds[bj];

    float4 v = make_float4(0.f, 0.f, 0.f, 0.f);
    int dy  = (int)y - s.y;
    int ady = dy < 0 ? -dy : dy;
    if (ady <= 5) {
        float wy = c_w[ady];
        float* vp = reinterpret_cast<float*>(&v);
#pragma unroll
        for (int k = 0; k < 4; k++) {
            int dx  = (int)(x0 + k) - s.x;
            int adx = dx < 0 ? -dx : dx;
            if (adx <= 5) vp[k] = wy * c_w[adx];
        }
    }
    out[tid] = v;
}

extern "C" void kernel_launch(void* const* d_in, const int* in_sizes, int n_in,
                              void* d_out, int out_size) {
    const float* joint = (const float*)d_in[0];

    // 1) project 1344 joints to pixel seeds
    seed_kernel<<<(BJ + 255) / 256, 256>>>(joint);

    // 2) write 64*21*256*256 floats, 4 per thread
    //    total threads = 1344 * 256 * 64 = 22,020,096 -> 86016 blocks
    const int total_vec4 = BJ * IMG * (IMG / 4);
    hm_kernel<<<total_vec4 / 256, 256>>>((float4*)d_out);
}